// round 3
// baseline (speedup 1.0000x reference)
#include <cuda_runtime.h>

#define NN   192
#define GRID 128

// ---- device-global scratch (no allocation allowed) ----
__device__ float g_SgT[NN * NN];
__device__ float g_X1[98304];   // x1 buffer  (max 512 pairs * 192)
__device__ float g_G1[98304];   // g1 = Sg @ x1
__device__ float g_P1[49152];   // enc1 out (pooled+relu)   [pt*16+o][n]
__device__ float g_P2[49152];   // enc2 out (pooled+relu)   [pt*32+o][n]
__device__ float g_P3[49152];   // dec1 out (plain)         [t*16+o][n]

// ---- replay-safe grid barrier (generation counter) ----
__device__ unsigned g_cnt = 0;
__device__ volatile unsigned g_gen = 0;

__device__ __forceinline__ void gsync() {
    __syncthreads();
    if (threadIdx.x == 0) {
        __threadfence();                       // release writes
        unsigned gen0 = g_gen;                 // == launch_gen + k at barrier k
        if (atomicAdd(&g_cnt, 1u) == GRID - 1) {
            g_cnt = 0;
            __threadfence();
            g_gen = gen0 + 1;
        } else {
            while (g_gen == gen0) { }
        }
        __threadfence();                       // acquire + L1D invalidate (CCTL.IVALL)
    }
    __syncthreads();
}

// x0 accessor: 0 = raw X (N,T) layout; 1 = buffer [(t*C+c)*NN+n];
//              5 = zero-stuff upsample by 2 + relu from half-T buffer
template <int X0M>
__device__ __forceinline__ float x0get(const float* __restrict__ P,
                                       int t, int c, int n, int C) {
    if (X0M == 0) return P[n * 32 + t];
    if (X0M == 1) return P[(t * C + c) * NN + n];
    if (t & 1) return 0.0f;
    float v = P[((t >> 1) * C + c) * NN + n];
    return v > 0.0f ? v : 0.0f;
}

// ---------------------------------------------------------------------------
// Encoder AB stage: for J pairs per block compute
//   g0[t], g0[t-1] (matvec on x0), x1 = s.(x0,g0), then g1 = Sg@x1.
// Stores x1 -> g_X1, g1 -> g_G1.
// ---------------------------------------------------------------------------
template <int J, int X0M>
__device__ void ab_enc(const float* __restrict__ P,
                       float s00, float s01, float s10, float s11,
                       int C, int T, int npairs, float* smx, int n, int b) {
    const int p0 = b * J;
    if (p0 >= npairs) return;
    float* xs0 = smx;            // [J][NN]
    float* xs1 = smx + J * NN;   // [J][NN]

#pragma unroll
    for (int j = 0; j < J; j++) {
        const int pc = min(p0 + j, npairs - 1);
        const int t = pc / C, c = pc % C, tm = (t + T - 1) % T;
        xs0[j * NN + n] = x0get<X0M>(P, t,  c, n, C);
        xs1[j * NN + n] = x0get<X0M>(P, tm, c, n, C);
    }
    __syncthreads();

    float g0t[J], g0m[J];
#pragma unroll
    for (int j = 0; j < J; j++) { g0t[j] = 0.0f; g0m[j] = 0.0f; }
#pragma unroll 4
    for (int m = 0; m < NN; m++) {
        const float sg = g_SgT[m * NN + n];
#pragma unroll
        for (int j = 0; j < J; j++) {
            g0t[j] = fmaf(sg, xs0[j * NN + m], g0t[j]);
            g0m[j] = fmaf(sg, xs1[j * NN + m], g0m[j]);
        }
    }
    __syncthreads();

#pragma unroll
    for (int j = 0; j < J; j++) {
        const float x1 = s00 * xs0[j * NN + n] + s01 * g0t[j]
                       + s10 * xs1[j * NN + n] + s11 * g0m[j];
        if (p0 + j < npairs) g_X1[(p0 + j) * NN + n] = x1;
        xs0[j * NN + n] = x1;
    }
    __syncthreads();

    float g1[J];
#pragma unroll
    for (int j = 0; j < J; j++) g1[j] = 0.0f;
#pragma unroll 4
    for (int m = 0; m < NN; m++) {
        const float sg = g_SgT[m * NN + n];
#pragma unroll
        for (int j = 0; j < J; j++) g1[j] = fmaf(sg, xs0[j * NN + m], g1[j]);
    }
#pragma unroll
    for (int j = 0; j < J; j++)
        if (p0 + j < npairs) g_G1[(p0 + j) * NN + n] = g1[j];
    __syncthreads();
}

// ---------------------------------------------------------------------------
// Decoder AB stage: x0 = zero-stuffed upsample(+relu) of half-T buffer P.
// g0 at odd time is zero -> only ONE g0 matvec per pair (u = t>>1).
//   t even: x1 = s00*x0u + s01*g0u ; t odd: x1 = s10*x0u + s11*g0u
// ---------------------------------------------------------------------------
template <int J>
__device__ void ab_dec(const float* __restrict__ P,
                       float s00, float s01, float s10, float s11,
                       int C, int T, int npairs, float* smx, int n, int b) {
    const int p0 = b * J;
    if (p0 >= npairs) return;
    float* xs0 = smx;

#pragma unroll
    for (int j = 0; j < J; j++) {
        const int pc = min(p0 + j, npairs - 1);
        const int t = pc / C, c = pc % C, u = t >> 1;
        float v = P[(u * C + c) * NN + n];
        xs0[j * NN + n] = v > 0.0f ? v : 0.0f;
    }
    __syncthreads();

    float g0[J];
#pragma unroll
    for (int j = 0; j < J; j++) g0[j] = 0.0f;
#pragma unroll 4
    for (int m = 0; m < NN; m++) {
        const float sg = g_SgT[m * NN + n];
#pragma unroll
        for (int j = 0; j < J; j++) g0[j] = fmaf(sg, xs0[j * NN + m], g0[j]);
    }
    __syncthreads();

#pragma unroll
    for (int j = 0; j < J; j++) {
        const int pc = min(p0 + j, npairs - 1);
        const int t = pc / C;
        const float ca = (t & 1) ? s10 : s00;
        const float cb = (t & 1) ? s11 : s01;
        const float x1 = ca * xs0[j * NN + n] + cb * g0[j];
        if (p0 + j < npairs) g_X1[(p0 + j) * NN + n] = x1;
        xs0[j * NN + n] = x1;
    }
    __syncthreads();

    float g1[J];
#pragma unroll
    for (int j = 0; j < J; j++) g1[j] = 0.0f;
#pragma unroll 4
    for (int m = 0; m < NN; m++) {
        const float sg = g_SgT[m * NN + n];
#pragma unroll
        for (int j = 0; j < J; j++) g1[j] = fmaf(sg, xs0[j * NN + m], g1[j]);
    }
#pragma unroll
    for (int j = 0; j < J; j++)
        if (p0 + j < npairs) g_G1[(p0 + j) * NN + n] = g1[j];
    __syncthreads();
}

// ---------------------------------------------------------------------------
// Projection: y[t][n][o] = sum_c x0*h[o][c][0] + x1*h[o][c][1] + x2*h[o][c][2]
//   x2 synthesized from x1/g1 at t, t-1.
// EMODE 0: pool time-pairs + relu; 1: plain; 2: COUT==1, transpose to out.
// ---------------------------------------------------------------------------
template <int CIN, int COUT, int OG, int EMODE, int X0M>
__device__ void proj(const float* __restrict__ P, const float* __restrict__ h,
                     float s00, float s01, float s10, float s11,
                     float* __restrict__ outp, int T, float* hs, int n, int b) {
    const int ogroups = COUT / OG;
    const int items = (EMODE == 0 ? T / 2 : T) * ogroups;

    for (int it = b; it < items; it += GRID) {
        const int og = it % ogroups, ti = it / ogroups;
        const int o0 = og * OG;
        for (int idx = n; idx < OG * CIN * 3; idx += NN)
            hs[idx] = h[o0 * CIN * 3 + idx];
        __syncthreads();

        const int nt = (EMODE == 0) ? 2 : 1;
        const int tb = (EMODE == 0) ? ti * 2 : ti;

        float best[OG];
#pragma unroll
        for (int o = 0; o < OG; o++) best[o] = -3.0e38f;

        for (int q = 0; q < nt; q++) {
            const int t = tb + q, tm = (t + T - 1) % T;
            float y[OG];
#pragma unroll
            for (int o = 0; o < OG; o++) y[o] = 0.0f;

            for (int c = 0; c < CIN; c++) {
                const float v0  = x0get<X0M>(P, t, c, n, CIN);
                const float v1  = g_X1[(t  * CIN + c) * NN + n];
                const float g1t = g_G1[(t  * CIN + c) * NN + n];
                const float v1m = g_X1[(tm * CIN + c) * NN + n];
                const float g1m = g_G1[(tm * CIN + c) * NN + n];
                const float v2  = s00 * v1 + s01 * g1t + s10 * v1m + s11 * g1m;
#pragma unroll
                for (int o = 0; o < OG; o++) {
                    const float* hp = &hs[(o * CIN + c) * 3];
                    y[o] = fmaf(v0, hp[0], y[o]);
                    y[o] = fmaf(v1, hp[1], y[o]);
                    y[o] = fmaf(v2, hp[2], y[o]);
                }
            }

            if (EMODE == 0) {
#pragma unroll
                for (int o = 0; o < OG; o++) best[o] = fmaxf(best[o], y[o]);
            } else if (EMODE == 1) {
#pragma unroll
                for (int o = 0; o < OG; o++)
                    outp[(t * COUT + o0 + o) * NN + n] = y[o];
            } else {
                outp[n * T + t] = y[0];
            }
        }
        if (EMODE == 0) {
#pragma unroll
            for (int o = 0; o < OG; o++)
                outp[(ti * COUT + o0 + o) * NN + n] = fmaxf(best[o], 0.0f);
        }
        __syncthreads();
    }
}

// ---------------------------------------------------------------------------
// The single fused kernel: 9 stages, 8 grid barriers.
// ---------------------------------------------------------------------------
__global__ void __launch_bounds__(NN, 1)
fused(const float* __restrict__ X,  const float* __restrict__ Sg,
      const float* __restrict__ s4,
      const float* __restrict__ he1, const float* __restrict__ he2,
      const float* __restrict__ hd1, const float* __restrict__ hd2,
      float* __restrict__ out) {
    const int n = threadIdx.x;
    const int b = blockIdx.x;
    __shared__ float smx[8 * NN];
    __shared__ float hs[768];
    __shared__ float tile[32][33];

    // S0: tiled transpose SgT[m][n] = Sg[n][m]  (36 tiles of 32x32)
    {
        const int lane = n & 31, grp = n >> 5;  // 6 row-groups
        for (int tidx = b; tidx < 36; tidx += GRID) {
            const int bi = tidx / 6, bj = tidx % 6;
            for (int r = grp; r < 32; r += 6)
                tile[r][lane] = Sg[(bi * 32 + r) * NN + bj * 32 + lane];
            __syncthreads();
            for (int r = grp; r < 32; r += 6)
                g_SgT[(bj * 32 + r) * NN + bi * 32 + lane] = tile[lane][r];
            __syncthreads();
        }
    }
    gsync();

    const float s00 = s4[0], s01 = s4[1], s10 = s4[2], s11 = s4[3];

    // ---- Encoder layer 1: T=32, C=1 -> 16, pool ----
    ab_enc<1, 0>(X, s00, s01, s10, s11, 1, 32, 32, smx, n, b);
    gsync();
    proj<1, 16, 16, 0, 0>(X, he1, s00, s01, s10, s11, g_P1, 32, hs, n, b);
    gsync();

    // ---- Encoder layer 2: T=16, C=16 -> 32, pool ----
    ab_enc<2, 1>(g_P1, s00, s01, s10, s11, 16, 16, 256, smx, n, b);
    gsync();
    proj<16, 32, 8, 0, 1>(g_P1, he2, s00, s01, s10, s11, g_P2, 16, hs, n, b);
    gsync();

    // ---- Decoder layer 1: up 8->16 (+relu), C=32 -> 16, plain ----
    ab_dec<4>(g_P2, s00, s01, s10, s11, 32, 16, 512, smx, n, b);
    gsync();
    proj<32, 16, 8, 1, 5>(g_P2, hd1, s00, s01, s10, s11, g_P3, 16, hs, n, b);
    gsync();

    // ---- Decoder layer 2: up 16->32 (+relu), C=16 -> 1, transpose out ----
    ab_dec<4>(g_P3, s00, s01, s10, s11, 16, 32, 512, smx, n, b);
    gsync();
    proj<16, 1, 1, 2, 5>(g_P3, hd2, s00, s01, s10, s11, out, 32, hs, n, b);
}

extern "C" void kernel_launch(void* const* d_in, const int* in_sizes, int n_in,
                              void* d_out, int out_size) {
    const float* X   = (const float*)d_in[0];  // (192, 32)
    const float* Sg  = (const float*)d_in[1];  // (192, 192)
    const float* s   = (const float*)d_in[2];  // (2, 2)
    const float* he1 = (const float*)d_in[3];  // (16, 1, 3)
    const float* he2 = (const float*)d_in[4];  // (32, 16, 3)
    const float* hd1 = (const float*)d_in[5];  // (16, 32, 3)
    const float* hd2 = (const float*)d_in[6];  // (1, 16, 3)
    float* out = (float*)d_out;                // (192, 32)

    fused<<<GRID, NN>>>(X, Sg, s, he1, he2, hd1, hd2, out);
}

// round 4
// speedup vs baseline: 2.1479x; 2.1479x over previous
#include <cuda_runtime.h>

#define NN    192
#define GRID  128
#define SROW  196                       // padded smem row stride (floats), 16B-aligned rows
#define SGS_F (NN * SROW)               // 37632 floats
#define XS_F  (8 * NN)                  // 1536 floats
#define HS_F  256
#define SMEM_BYTES ((SGS_F + XS_F + HS_F) * 4)   // 157,696 B

// ---- device-global scratch (no allocation allowed) ----
__device__ float g_X1[98304];   // x1  (max 512 pairs * 192)
__device__ float g_G1[98304];   // g1 = Sg @ x1
__device__ float g_P1[49152];   // enc1 out (pooled+relu)  [(pt*16+o)*NN+n]
__device__ float g_P2[49152];   // enc2 out (pooled+relu)
__device__ float g_P3[49152];   // dec1 out (plain)

// ---- replay-safe grid barrier (generation counter) ----
__device__ unsigned g_cnt = 0;
__device__ volatile unsigned g_gen = 0;

__device__ __forceinline__ void gsync() {
    __syncthreads();
    if (threadIdx.x == 0) {
        __threadfence();                       // release
        unsigned gen0 = g_gen;
        if (atomicAdd(&g_cnt, 1u) == GRID - 1) {
            g_cnt = 0;
            __threadfence();
            g_gen = gen0 + 1;
        } else {
            while (g_gen == gen0) __nanosleep(32);
        }
        __threadfence();                       // acquire (+L1D inval)
    }
    __syncthreads();
}

// x0 accessor: 0 = raw X (N,T); 1 = buffer [(t*C+c)*NN+n]; 5 = up2+relu from half-T buffer
template <int X0M>
__device__ __forceinline__ float x0get(const float* __restrict__ P,
                                       int t, int c, int n, int C) {
    if (X0M == 0) return P[n * 32 + t];
    if (X0M == 1) return P[(t * C + c) * NN + n];
    if (t & 1) return 0.0f;
    float v = P[((t >> 1) * C + c) * NN + n];
    return v > 0.0f ? v : 0.0f;
}

// vectorized matvec core: acc[j] += dot(sg_row[n], xsv[j])
template <int J>
__device__ __forceinline__ void mv(const float* __restrict__ sgs,
                                   const float* __restrict__ xsv,
                                   float* acc, int n) {
    const float4* __restrict__ srow = (const float4*)(sgs + n * SROW);
#pragma unroll 4
    for (int q = 0; q < NN / 4; q++) {
        const float4 sg = srow[q];
#pragma unroll
        for (int j = 0; j < J; j++) {
            const float4 xv = ((const float4*)(xsv + j * NN))[q];
            acc[j] = fmaf(sg.x, xv.x, acc[j]);
            acc[j] = fmaf(sg.y, xv.y, acc[j]);
            acc[j] = fmaf(sg.z, xv.z, acc[j]);
            acc[j] = fmaf(sg.w, xv.w, acc[j]);
        }
    }
}

// ---------------------------------------------------------------------------
// Encoder AB: per block J pairs -> g0[t], g0[t-1], x1, g1. x1->g_X1, g1->g_G1.
// ---------------------------------------------------------------------------
template <int J, int X0M>
__device__ void ab_enc(const float* __restrict__ P, const float* __restrict__ sgs,
                       float* xs, float s00, float s01, float s10, float s11,
                       int C, int T, int npairs, int n, int b) {
    const int p0 = b * J;
    if (p0 >= npairs) return;
    float* xs0 = xs;            // [J][NN]
    float* xs1 = xs + J * NN;   // [J][NN]

#pragma unroll
    for (int j = 0; j < J; j++) {
        const int pc = min(p0 + j, npairs - 1);
        const int t = pc / C, c = pc % C, tm = (t + T - 1) % T;
        xs0[j * NN + n] = x0get<X0M>(P, t,  c, n, C);
        xs1[j * NN + n] = x0get<X0M>(P, tm, c, n, C);
    }
    __syncthreads();

    float g0t[J], g0m[J];
#pragma unroll
    for (int j = 0; j < J; j++) { g0t[j] = 0.0f; g0m[j] = 0.0f; }
    mv<J>(sgs, xs0, g0t, n);
    mv<J>(sgs, xs1, g0m, n);
    __syncthreads();

#pragma unroll
    for (int j = 0; j < J; j++) {
        const float x1 = s00 * xs0[j * NN + n] + s01 * g0t[j]
                       + s10 * xs1[j * NN + n] + s11 * g0m[j];
        if (p0 + j < npairs) g_X1[(p0 + j) * NN + n] = x1;
        xs0[j * NN + n] = x1;
    }
    __syncthreads();

    float g1[J];
#pragma unroll
    for (int j = 0; j < J; j++) g1[j] = 0.0f;
    mv<J>(sgs, xs0, g1, n);
#pragma unroll
    for (int j = 0; j < J; j++)
        if (p0 + j < npairs) g_G1[(p0 + j) * NN + n] = g1[j];
    __syncthreads();
}

// ---------------------------------------------------------------------------
// Decoder AB: x0 = zero-stuff up2 (+relu). g0 at odd t is zero -> 1 g0 matvec.
//   t even: x1 = s00*x0u + s01*g0u ; t odd: x1 = s10*x0u + s11*g0u  (u = t>>1)
// ---------------------------------------------------------------------------
template <int J>
__device__ void ab_dec(const float* __restrict__ P, const float* __restrict__ sgs,
                       float* xs, float s00, float s01, float s10, float s11,
                       int C, int T, int npairs, int n, int b) {
    const int p0 = b * J;
    if (p0 >= npairs) return;
    float* xs0 = xs;

#pragma unroll
    for (int j = 0; j < J; j++) {
        const int pc = min(p0 + j, npairs - 1);
        const int t = pc / C, c = pc % C, u = t >> 1;
        float v = P[(u * C + c) * NN + n];
        xs0[j * NN + n] = v > 0.0f ? v : 0.0f;
    }
    __syncthreads();

    float g0[J];
#pragma unroll
    for (int j = 0; j < J; j++) g0[j] = 0.0f;
    mv<J>(sgs, xs0, g0, n);
    __syncthreads();

#pragma unroll
    for (int j = 0; j < J; j++) {
        const int pc = min(p0 + j, npairs - 1);
        const int t = pc / C;
        const float ca = (t & 1) ? s10 : s00;
        const float cb = (t & 1) ? s11 : s01;
        const float x1 = ca * xs0[j * NN + n] + cb * g0[j];
        if (p0 + j < npairs) g_X1[(p0 + j) * NN + n] = x1;
        xs0[j * NN + n] = x1;
    }
    __syncthreads();

    float g1[J];
#pragma unroll
    for (int j = 0; j < J; j++) g1[j] = 0.0f;
    mv<J>(sgs, xs0, g1, n);
#pragma unroll
    for (int j = 0; j < J; j++)
        if (p0 + j < npairs) g_G1[(p0 + j) * NN + n] = g1[j];
    __syncthreads();
}

// ---------------------------------------------------------------------------
// Projection: y = sum_c x0*h0 + x1*h1 + x2*h2, x2 synthesized from x1/g1.
// EMODE 0: pool time pairs + relu; 1: plain; 2: COUT==1, transpose to out.
// ---------------------------------------------------------------------------
template <int CIN, int COUT, int OG, int EMODE, int X0M>
__device__ void proj(const float* __restrict__ P, const float* __restrict__ h,
                     float s00, float s01, float s10, float s11,
                     float* __restrict__ outp, int T, float* hs, int n, int b) {
    const int ogroups = COUT / OG;
    const int items = (EMODE == 0 ? T / 2 : T) * ogroups;

    for (int it = b; it < items; it += GRID) {
        const int og = it % ogroups, ti = it / ogroups;
        const int o0 = og * OG;
        for (int idx = n; idx < OG * CIN * 3; idx += NN)
            hs[idx] = h[o0 * CIN * 3 + idx];
        __syncthreads();

        const int nt = (EMODE == 0) ? 2 : 1;
        const int tb = (EMODE == 0) ? ti * 2 : ti;

        float best[OG];
#pragma unroll
        for (int o = 0; o < OG; o++) best[o] = -3.0e38f;

        for (int q = 0; q < nt; q++) {
            const int t = tb + q, tm = (t + T - 1) % T;
            float y[OG];
#pragma unroll
            for (int o = 0; o < OG; o++) y[o] = 0.0f;

#pragma unroll 4
            for (int c = 0; c < CIN; c++) {
                const float v0  = x0get<X0M>(P, t, c, n, CIN);
                const float v1  = g_X1[(t  * CIN + c) * NN + n];
                const float g1t = g_G1[(t  * CIN + c) * NN + n];
                const float v1m = g_X1[(tm * CIN + c) * NN + n];
                const float g1m = g_G1[(tm * CIN + c) * NN + n];
                const float v2  = s00 * v1 + s01 * g1t + s10 * v1m + s11 * g1m;
#pragma unroll
                for (int o = 0; o < OG; o++) {
                    const float* hp = &hs[(o * CIN + c) * 3];
                    y[o] = fmaf(v0, hp[0], y[o]);
                    y[o] = fmaf(v1, hp[1], y[o]);
                    y[o] = fmaf(v2, hp[2], y[o]);
                }
            }

            if (EMODE == 0) {
#pragma unroll
                for (int o = 0; o < OG; o++) best[o] = fmaxf(best[o], y[o]);
            } else if (EMODE == 1) {
#pragma unroll
                for (int o = 0; o < OG; o++)
                    outp[(t * COUT + o0 + o) * NN + n] = y[o];
            } else {
                outp[n * T + t] = y[0];
            }
        }
        if (EMODE == 0) {
#pragma unroll
            for (int o = 0; o < OG; o++)
                outp[(ti * COUT + o0 + o) * NN + n] = fmaxf(best[o], 0.0f);
        }
        __syncthreads();
    }
}

// ---------------------------------------------------------------------------
// Single fused kernel: smem-resident Sg, 8 stages, 7 grid barriers.
// ---------------------------------------------------------------------------
extern __shared__ float sm[];
__global__ void __launch_bounds__(NN, 1)
fused(const float* __restrict__ X,  const float* __restrict__ Sg,
      const float* __restrict__ s4,
      const float* __restrict__ he1, const float* __restrict__ he2,
      const float* __restrict__ hd1, const float* __restrict__ hd2,
      float* __restrict__ out) {
    const int n = threadIdx.x;
    const int b = blockIdx.x;
    float* sgs = sm;                 // [NN][SROW] row-major padded copy of Sg
    float* xs  = sm + SGS_F;         // matvec staging
    float* hs  = xs + XS_F;          // filter tile

    // Stage 0 (block-local): copy Sg rows into padded smem (coalesced reads,
    // conflict-free writes: addr a*196+n -> banks (4a+n)&31 distinct over n).
#pragma unroll 4
    for (int a = 0; a < NN; a++)
        sgs[a * SROW + n] = Sg[a * NN + n];
    __syncthreads();

    const float s00 = s4[0], s01 = s4[1], s10 = s4[2], s11 = s4[3];

    // ---- Encoder layer 1: T=32, C=1 -> 16, pool ----
    ab_enc<1, 0>(X, sgs, xs, s00, s01, s10, s11, 1, 32, 32, n, b);
    gsync();
    proj<1, 16, 2, 0, 0>(X, he1, s00, s01, s10, s11, g_P1, 32, hs, n, b);
    gsync();

    // ---- Encoder layer 2: T=16, C=16 -> 32, pool ----
    ab_enc<2, 1>(g_P1, sgs, xs, s00, s01, s10, s11, 16, 16, 256, n, b);
    gsync();
    proj<16, 32, 2, 0, 1>(g_P1, he2, s00, s01, s10, s11, g_P2, 16, hs, n, b);
    gsync();

    // ---- Decoder layer 1: up 8->16 (+relu), C=32 -> 16, plain ----
    ab_dec<4>(g_P2, sgs, xs, s00, s01, s10, s11, 32, 16, 512, n, b);
    gsync();
    proj<32, 16, 2, 1, 5>(g_P2, hd1, s00, s01, s10, s11, g_P3, 16, hs, n, b);
    gsync();

    // ---- Decoder layer 2: up 16->32 (+relu), C=16 -> 1, transpose out ----
    ab_dec<4>(g_P3, sgs, xs, s00, s01, s10, s11, 16, 32, 512, n, b);
    gsync();
    proj<16, 1, 1, 2, 5>(g_P3, hd2, s00, s01, s10, s11, out, 32, hs, n, b);
}

extern "C" void kernel_launch(void* const* d_in, const int* in_sizes, int n_in,
                              void* d_out, int out_size) {
    const float* X   = (const float*)d_in[0];  // (192, 32)
    const float* Sg  = (const float*)d_in[1];  // (192, 192)
    const float* s   = (const float*)d_in[2];  // (2, 2)
    const float* he1 = (const float*)d_in[3];  // (16, 1, 3)
    const float* he2 = (const float*)d_in[4];  // (32, 16, 3)
    const float* hd1 = (const float*)d_in[5];  // (16, 32, 3)
    const float* hd2 = (const float*)d_in[6];  // (1, 16, 3)
    float* out = (float*)d_out;                // (192, 32)

    cudaFuncSetAttribute(fused, cudaFuncAttributeMaxDynamicSharedMemorySize,
                         SMEM_BYTES);
    fused<<<GRID, NN, SMEM_BYTES>>>(X, Sg, s, he1, he2, hd1, hd2, out);
}